// round 11
// baseline (speedup 1.0000x reference)
#include <cuda_runtime.h>
#include <cuda_fp16.h>
#include <cstdint>
#include <math.h>

#define BATCH 16
#define CDIM  512
#define HH    64
#define WW    64
#define NDIM  4096  // H*W
#define TOT_ELEMS (BATCH * CDIM * NDIM)   // 33,554,432

// Scratch (allocation-guard safe): fp16 copies of inputs + fp32 energy.
__device__ __half g_hq [TOT_ELEMS];
__device__ __half g_hkv[TOT_ELEMS];
__device__ float  g_energy[BATCH * (size_t)CDIM * CDIM];

// ---------------------------------------------------------------------------
// Convert fp32 inputs to fp16 scratch. One float4 per tensor per thread.
// ---------------------------------------------------------------------------
__global__ __launch_bounds__(256) void convert_kernel(const float4* __restrict__ q4,
                                                      const float4* __restrict__ kv4) {
    const int i = blockIdx.x * 256 + threadIdx.x;     // < TOT_ELEMS/4
    float4 a = q4[i];
    float4 b = kv4[i];
    __half2* hq  = (__half2*)g_hq;
    __half2* hkv = (__half2*)g_hkv;
    hq [2 * i]     = __floats2half2_rn(a.x, a.y);
    hq [2 * i + 1] = __floats2half2_rn(a.z, a.w);
    hkv[2 * i]     = __floats2half2_rn(b.x, b.y);
    hkv[2 * i + 1] = __floats2half2_rn(b.z, b.w);
}

// ---------------------------------------------------------------------------
// HGEMM: approx energy[b,c,d] = sum_n q[c,n]*kv[d,n], fp16 in, fp32 acc.
// Tile BM=128 x BN=64, BK=64 halves (128 B rows, SW128-style xor swizzle).
// 256 threads = 8 warps (4 along m x 2 along n), warp tile 32x32,
// mma.sync.m16n8k16 fragments via ldmatrix.
// ---------------------------------------------------------------------------
#define BM 128
#define BN 64
#define BK 64

__device__ __forceinline__ int sw_idx(int row, int chunk) {
    // row*BK + swizzled 8-half chunk offset
    return row * BK + ((chunk ^ (row & 7)) << 3);
}

__device__ __forceinline__ void ldsm4(uint32_t& r0, uint32_t& r1, uint32_t& r2,
                                      uint32_t& r3, uint32_t addr) {
    asm volatile("ldmatrix.sync.aligned.m8n8.x4.shared.b16 {%0,%1,%2,%3}, [%4];"
                 : "=r"(r0), "=r"(r1), "=r"(r2), "=r"(r3) : "r"(addr));
}

__device__ __forceinline__ void mma16816(float* c, const uint32_t* a, const uint32_t* b) {
    asm volatile("mma.sync.aligned.m16n8k16.row.col.f32.f16.f16.f32 "
                 "{%0,%1,%2,%3}, {%4,%5,%6,%7}, {%8,%9}, {%0,%1,%2,%3};"
                 : "+f"(c[0]), "+f"(c[1]), "+f"(c[2]), "+f"(c[3])
                 : "r"(a[0]), "r"(a[1]), "r"(a[2]), "r"(a[3]),
                   "r"(b[0]), "r"(b[1]));
}

__global__ __launch_bounds__(256) void hgemm_kernel() {
    __shared__ __align__(16) __half As[BM * BK];
    __shared__ __align__(16) __half Bs[BN * BK];

    const int b = blockIdx.z;
    const __half* Ab = g_hq  + (size_t)b * CDIM * NDIM + (size_t)blockIdx.y * BM * NDIM;
    const __half* Bb = g_hkv + (size_t)b * CDIM * NDIM + (size_t)blockIdx.x * BN * NDIM;

    const int t    = threadIdx.x;
    const int lane = t & 31;
    const int wid  = t >> 5;
    const int wm   = wid & 3;         // 0..3 -> m offset
    const int wn   = wid >> 2;        // 0..1 -> n offset
    const int mbase = wm * 32;
    const int nbase = wn * 32;

    // global-load mapping: 8 threads per 128-B row
    const int ldRow   = t >> 3;       // 0..31
    const int ldChunk = t & 7;        // 0..7

    const uint32_t asU = (uint32_t)__cvta_generic_to_shared(As);
    const uint32_t bsU = (uint32_t)__cvta_generic_to_shared(Bs);

    float acc[2][4][4];
#pragma unroll
    for (int mi = 0; mi < 2; mi++)
#pragma unroll
        for (int ni = 0; ni < 4; ni++)
#pragma unroll
            for (int k = 0; k < 4; k++) acc[mi][ni][k] = 0.0f;

    // ---- load chunk 0 into smem ----
    {
        const __half* pa = Ab + ldChunk * 8;
        const __half* pb = Bb + ldChunk * 8;
#pragma unroll
        for (int i = 0; i < 4; i++) {
            int r = ldRow + i * 32;
            *(uint4*)&As[sw_idx(r, ldChunk)] = *(const uint4*)(pa + (size_t)r * NDIM);
        }
#pragma unroll
        for (int i = 0; i < 2; i++) {
            int r = ldRow + i * 32;
            *(uint4*)&Bs[sw_idx(r, ldChunk)] = *(const uint4*)(pb + (size_t)r * NDIM);
        }
    }
    __syncthreads();

    const int NCHUNK = NDIM / BK;   // 64
    for (int kk = 0; kk < NCHUNK; kk++) {
        const bool notlast = (kk + 1 < NCHUNK);
        uint4 pa[4], pb[2];
        if (notlast) {
            const __half* gpa = Ab + (kk + 1) * BK + ldChunk * 8;
            const __half* gpb = Bb + (kk + 1) * BK + ldChunk * 8;
#pragma unroll
            for (int i = 0; i < 4; i++)
                pa[i] = *(const uint4*)(gpa + (size_t)(ldRow + i * 32) * NDIM);
#pragma unroll
            for (int i = 0; i < 2; i++)
                pb[i] = *(const uint4*)(gpb + (size_t)(ldRow + i * 32) * NDIM);
        }

        // ---- compute 4 k16 steps from smem ----
#pragma unroll
        for (int s = 0; s < 4; s++) {
            uint32_t afr[2][4];
            uint32_t bfr[4][2];
#pragma unroll
            for (int mi = 0; mi < 2; mi++) {
                int row   = mbase + mi * 16 + (lane & 15);
                int chunk = 2 * s + (lane >> 4);
                uint32_t addr = asU + (uint32_t)(sw_idx(row, chunk) * 2);
                ldsm4(afr[mi][0], afr[mi][1], afr[mi][2], afr[mi][3], addr);
            }
#pragma unroll
            for (int p = 0; p < 2; p++) {
                int row   = nbase + p * 16 + (lane & 7) + ((lane >> 4) << 3);
                int chunk = 2 * s + ((lane >> 3) & 1);
                uint32_t addr = bsU + (uint32_t)(sw_idx(row, chunk) * 2);
                ldsm4(bfr[2 * p][0], bfr[2 * p][1], bfr[2 * p + 1][0], bfr[2 * p + 1][1], addr);
            }
#pragma unroll
            for (int mi = 0; mi < 2; mi++)
#pragma unroll
                for (int ni = 0; ni < 4; ni++)
                    mma16816(acc[mi][ni], afr[mi], bfr[ni]);
        }
        __syncthreads();

        if (notlast) {
#pragma unroll
            for (int i = 0; i < 4; i++)
                *(uint4*)&As[sw_idx(ldRow + i * 32, ldChunk)] = pa[i];
#pragma unroll
            for (int i = 0; i < 2; i++)
                *(uint4*)&Bs[sw_idx(ldRow + i * 32, ldChunk)] = pb[i];
            __syncthreads();
        }
    }

    // ---- epilogue: write fp32 energies ----
    float* Eb = g_energy + (size_t)b * CDIM * CDIM;
    const int c0 = blockIdx.y * BM + mbase;
    const int d0 = blockIdx.x * BN + nbase;
#pragma unroll
    for (int mi = 0; mi < 2; mi++) {
#pragma unroll
        for (int ni = 0; ni < 4; ni++) {
            int r = c0 + mi * 16 + (lane >> 2);
            int c = d0 + ni * 8 + ((lane & 3) << 1);
            Eb[(size_t)r * CDIM + c]           = acc[mi][ni][0];
            Eb[(size_t)r * CDIM + c + 1]       = acc[mi][ni][1];
            Eb[(size_t)(r + 8) * CDIM + c]     = acc[mi][ni][2];
            Eb[(size_t)(r + 8) * CDIM + c + 1] = acc[mi][ni][3];
        }
    }
}

// ---------------------------------------------------------------------------
// Fused attention-apply v2:
//  - approx min over row energies; select candidates e - min < 36
//    (covers exact threshold 34 + fp16-GEMM error with huge sigma margin)
//  - recompute candidate energies EXACTLY in fp32 (q row staged in smem)
//  - exact softmax weights over candidates (dropped terms < 2e-15 each)
//  - sparse gather out = sum w_d * kv[d,:], then per-64 softmax -> d_out
// One block (256 threads) per (b,c) row.
// ---------------------------------------------------------------------------
__global__ __launch_bounds__(256) void attn_apply_kernel(const float* __restrict__ q,
                                                         const float* __restrict__ kv,
                                                         float* __restrict__ out) {
    const int row = blockIdx.x;            // b*512 + c
    const int b   = row >> 9;
    const float* E    = g_energy + (size_t)row * CDIM;
    const float* qrow = q + (size_t)row * NDIM;
    const float* kvb  = kv + (size_t)b * CDIM * NDIM;
    float* O = out + (size_t)row * NDIM;

    __shared__ float sRed[8];
    __shared__ float sBuf[NDIM];    // q row, later reused for out row
    __shared__ float sEW[CDIM];     // exact energies, then weights
    __shared__ int   sIdx[CDIM];
    __shared__ int   sCount;

    const int t    = threadIdx.x;
    const int lane = t & 31;
    const int wp   = t >> 5;

    const float e0 = E[t];
    const float e1 = E[t + 256];

    // ---- approx min over the 512 energies ----
    float mn = fminf(e0, e1);
#pragma unroll
    for (int off = 16; off > 0; off >>= 1)
        mn = fminf(mn, __shfl_xor_sync(0xffffffffu, mn, off));
    if (lane == 0) sRed[wp] = mn;
    if (t == 0) sCount = 0;
    __syncthreads();
    mn = sRed[0];
#pragma unroll
    for (int i = 1; i < 8; i++) mn = fminf(mn, sRed[i]);

    // ---- candidate selection + stage q row in smem ----
    if (e0 - mn < 36.0f) { int k = atomicAdd(&sCount, 1); sIdx[k] = t; }
    if (e1 - mn < 36.0f) { int k = atomicAdd(&sCount, 1); sIdx[k] = t + 256; }
#pragma unroll
    for (int j = 0; j < 16; j++) sBuf[t + 256 * j] = qrow[t + 256 * j];
    __syncthreads();
    const int cnt = sCount;

    // ---- exact fp32 energies for candidates (one warp per candidate) ----
    for (int i = wp; i < cnt; i += 8) {
        const float* kr = kvb + (size_t)sIdx[i] * NDIM;
        float sum = 0.0f;
#pragma unroll 8
        for (int k = lane; k < NDIM; k += 32)
            sum += sBuf[k] * __ldg(&kr[k]);
#pragma unroll
        for (int off = 16; off > 0; off >>= 1)
            sum += __shfl_xor_sync(0xffffffffu, sum, off);
        if (lane == 0) sEW[i] = sum;
    }
    __syncthreads();

    // ---- exact min + denominator over candidates (all threads identical) ----
    float m = 3.4e38f;
    for (int i = 0; i < cnt; i++) m = fminf(m, sEW[i]);
    float s = 0.0f;
    for (int i = 0; i < cnt; i++) s += expf(m - sEW[i]);
    const float inv = 1.0f / s;
    __syncthreads();
    for (int i = t; i < cnt; i += 256)
        sEW[i] = expf(m - sEW[i]) * inv;   // in-place weights
    __syncthreads();

    // ---- sparse gather-accumulate ----
    float acc[16];
#pragma unroll
    for (int k = 0; k < 16; k++) acc[k] = 0.0f;
    for (int i = 0; i < cnt; i++) {
        const float* kr = kvb + (size_t)sIdx[i] * NDIM;
        const float w = sEW[i];
#pragma unroll
        for (int k = 0; k < 16; k++)
            acc[k] += w * __ldg(&kr[t + 256 * k]);
    }
    __syncthreads();   // done with sBuf-as-q
#pragma unroll
    for (int k = 0; k < 16; k++) sBuf[t + 256 * k] = acc[k];
    __syncthreads();

    // ---- final softmax over each 64-wide segment; 8 warps x 8 segments ----
#pragma unroll
    for (int sgi = 0; sgi < 8; sgi++) {
        const int base = (wp * 8 + sgi) * 64;
        const float v0 = sBuf[base + lane];
        const float v1 = sBuf[base + lane + 32];
        float mx = fmaxf(v0, v1);
#pragma unroll
        for (int off = 16; off > 0; off >>= 1)
            mx = fmaxf(mx, __shfl_xor_sync(0xffffffffu, mx, off));
        const float q0 = expf(v0 - mx);
        const float q1 = expf(v1 - mx);
        float ss = q0 + q1;
#pragma unroll
        for (int off = 16; off > 0; off >>= 1)
            ss += __shfl_xor_sync(0xffffffffu, ss, off);
        const float iv = 1.0f / ss;
        O[base + lane]      = q0 * iv;
        O[base + lane + 32] = q1 * iv;
    }
}

// ---------------------------------------------------------------------------
extern "C" void kernel_launch(void* const* d_in, const int* in_sizes, int n_in,
                              void* d_out, int out_size) {
    const float* kv = (const float*)d_in[0];  // x_training
    const float* q  = (const float*)d_in[1];  // x_pre
    float* out = (float*)d_out;

    convert_kernel<<<TOT_ELEMS / 4 / 256, 256>>>((const float4*)q, (const float4*)kv);

    dim3 g1(CDIM / BN, CDIM / BM, BATCH);   // (8, 4, 16)
    hgemm_kernel<<<g1, 256>>>();

    attn_apply_kernel<<<BATCH * CDIM, 256>>>(q, kv, out);
}

// round 16
// speedup vs baseline: 1.1367x; 1.1367x over previous
#include <cuda_runtime.h>
#include <cuda_fp16.h>
#include <cstdint>
#include <math.h>

#define BATCH 16
#define CDIM  512
#define HH    64
#define WW    64
#define NDIM  4096  // H*W
#define TOT_ELEMS (BATCH * CDIM * NDIM)   // 33,554,432

// Scratch (allocation-guard safe): fp16 copies of inputs + fp32 energy.
__device__ __half g_hq [TOT_ELEMS];
__device__ __half g_hkv[TOT_ELEMS];
__device__ float  g_energy[BATCH * (size_t)CDIM * CDIM];

// ---------------------------------------------------------------------------
// Convert fp32 inputs to fp16 scratch. One float4 per tensor per thread.
// (83% DRAM roofline already)
// ---------------------------------------------------------------------------
__global__ __launch_bounds__(256) void convert_kernel(const float4* __restrict__ q4,
                                                      const float4* __restrict__ kv4) {
    const int i = blockIdx.x * 256 + threadIdx.x;     // < TOT_ELEMS/4
    float4 a = q4[i];
    float4 b = kv4[i];
    __half2* hq  = (__half2*)g_hq;
    __half2* hkv = (__half2*)g_hkv;
    hq [2 * i]     = __floats2half2_rn(a.x, a.y);
    hq [2 * i + 1] = __floats2half2_rn(a.z, a.w);
    hkv[2 * i]     = __floats2half2_rn(b.x, b.y);
    hkv[2 * i + 1] = __floats2half2_rn(b.z, b.w);
}

// ---------------------------------------------------------------------------
// HGEMM: approx energy[b,c,d] = sum_n q[c,n]*kv[d,n], fp16 in, fp32 acc.
// Tile BM=128 x BN=128, BK=64 halves (128 B rows, xor-8 swizzle).
// 256 threads = 8 warps (2 m x 4 n), warp tile 64x32, mma.m16n8k16.
// cp.async double-buffered smem pipeline (64 KB dynamic).
// ---------------------------------------------------------------------------
#define BM 128
#define BN 128
#define BK 64
#define HGEMM_SMEM (2 * (BM + BN) * BK * 2)   // 65536 bytes

__device__ __forceinline__ int sw_idx(int row, int chunk) {
    return row * BK + ((chunk ^ (row & 7)) << 3);
}

__device__ __forceinline__ void ldsm4(uint32_t& r0, uint32_t& r1, uint32_t& r2,
                                      uint32_t& r3, uint32_t addr) {
    asm volatile("ldmatrix.sync.aligned.m8n8.x4.shared.b16 {%0,%1,%2,%3}, [%4];"
                 : "=r"(r0), "=r"(r1), "=r"(r2), "=r"(r3) : "r"(addr));
}

__device__ __forceinline__ void mma16816(float* c, const uint32_t* a, const uint32_t* b) {
    asm volatile("mma.sync.aligned.m16n8k16.row.col.f32.f16.f16.f32 "
                 "{%0,%1,%2,%3}, {%4,%5,%6,%7}, {%8,%9}, {%0,%1,%2,%3};"
                 : "+f"(c[0]), "+f"(c[1]), "+f"(c[2]), "+f"(c[3])
                 : "r"(a[0]), "r"(a[1]), "r"(a[2]), "r"(a[3]),
                   "r"(b[0]), "r"(b[1]));
}

__device__ __forceinline__ void cp_async16(uint32_t dst, const void* src) {
    asm volatile("cp.async.cg.shared.global [%0], [%1], 16;" :: "r"(dst), "l"(src));
}
__device__ __forceinline__ void cp_commit() {
    asm volatile("cp.async.commit_group;");
}
template<int N> __device__ __forceinline__ void cp_wait() {
    asm volatile("cp.async.wait_group %0;" :: "n"(N));
}

__global__ __launch_bounds__(256) void hgemm_kernel() {
    extern __shared__ __align__(16) __half dynsmem[];
    __half* As = dynsmem;                  // [2][BM*BK]
    __half* Bs = dynsmem + 2 * BM * BK;    // [2][BN*BK]

    const int b = blockIdx.z;
    const __half* Ab = g_hq  + (size_t)b * CDIM * NDIM + (size_t)blockIdx.y * BM * NDIM;
    const __half* Bb = g_hkv + (size_t)b * CDIM * NDIM + (size_t)blockIdx.x * BN * NDIM;

    const int t    = threadIdx.x;
    const int lane = t & 31;
    const int wid  = t >> 5;
    const int wm   = wid & 1;          // 0..1 -> m offset (64)
    const int wn   = wid >> 1;         // 0..3 -> n offset (32)
    const int mbase = wm * 64;
    const int nbase = wn * 32;

    // global-load mapping: 8 threads per 128-B row
    const int ldRow   = t >> 3;        // 0..31
    const int ldChunk = t & 7;         // 0..7

    const uint32_t asU = (uint32_t)__cvta_generic_to_shared(As);
    const uint32_t bsU = (uint32_t)__cvta_generic_to_shared(Bs);

    float acc[4][4][4];
#pragma unroll
    for (int mi = 0; mi < 4; mi++)
#pragma unroll
        for (int ni = 0; ni < 4; ni++)
#pragma unroll
            for (int k = 0; k < 4; k++) acc[mi][ni][k] = 0.0f;

    // async stage loader
    auto load_stage = [&](int stage, int kk) {
        const __half* gpa = Ab + kk * BK + ldChunk * 8;
        const __half* gpb = Bb + kk * BK + ldChunk * 8;
        const uint32_t aS = asU + (uint32_t)(stage * BM * BK * 2);
        const uint32_t bS = bsU + (uint32_t)(stage * BN * BK * 2);
#pragma unroll
        for (int i = 0; i < 4; i++) {
            int r = ldRow + i * 32;
            cp_async16(aS + (uint32_t)(sw_idx(r, ldChunk) * 2), gpa + (size_t)r * NDIM);
        }
#pragma unroll
        for (int i = 0; i < 4; i++) {
            int r = ldRow + i * 32;
            cp_async16(bS + (uint32_t)(sw_idx(r, ldChunk) * 2), gpb + (size_t)r * NDIM);
        }
        cp_commit();
    };

    const int NCHUNK = NDIM / BK;   // 64
    load_stage(0, 0);

    for (int kk = 0; kk < NCHUNK; kk++) {
        if (kk + 1 < NCHUNK) {
            load_stage((kk + 1) & 1, kk + 1);
            cp_wait<1>();
        } else {
            cp_wait<0>();
        }
        __syncthreads();

        const uint32_t aS = asU + (uint32_t)((kk & 1) * BM * BK * 2);
        const uint32_t bS = bsU + (uint32_t)((kk & 1) * BN * BK * 2);

#pragma unroll
        for (int s = 0; s < 4; s++) {
            uint32_t afr[4][4];
            uint32_t bfr[4][2];
#pragma unroll
            for (int mi = 0; mi < 4; mi++) {
                int row   = mbase + mi * 16 + (lane & 15);
                int chunk = 2 * s + (lane >> 4);
                ldsm4(afr[mi][0], afr[mi][1], afr[mi][2], afr[mi][3],
                      aS + (uint32_t)(sw_idx(row, chunk) * 2));
            }
#pragma unroll
            for (int p = 0; p < 2; p++) {
                int row   = nbase + p * 16 + (lane & 7) + ((lane >> 4) << 3);
                int chunk = 2 * s + ((lane >> 3) & 1);
                ldsm4(bfr[2 * p][0], bfr[2 * p][1], bfr[2 * p + 1][0], bfr[2 * p + 1][1],
                      bS + (uint32_t)(sw_idx(row, chunk) * 2));
            }
#pragma unroll
            for (int mi = 0; mi < 4; mi++)
#pragma unroll
                for (int ni = 0; ni < 4; ni++)
                    mma16816(acc[mi][ni], afr[mi], bfr[ni]);
        }
        __syncthreads();
    }

    // ---- epilogue: write fp32 energies ----
    float* Eb = g_energy + (size_t)b * CDIM * CDIM;
    const int c0 = blockIdx.y * BM + mbase;
    const int d0 = blockIdx.x * BN + nbase;
#pragma unroll
    for (int mi = 0; mi < 4; mi++) {
#pragma unroll
        for (int ni = 0; ni < 4; ni++) {
            int r = c0 + mi * 16 + (lane >> 2);
            int c = d0 + ni * 8 + ((lane & 3) << 1);
            Eb[(size_t)r * CDIM + c]           = acc[mi][ni][0];
            Eb[(size_t)r * CDIM + c + 1]       = acc[mi][ni][1];
            Eb[(size_t)(r + 8) * CDIM + c]     = acc[mi][ni][2];
            Eb[(size_t)(r + 8) * CDIM + c + 1] = acc[mi][ni][3];
        }
    }
}

// ---------------------------------------------------------------------------
// Fused attention-apply:
//  - approx min over row energies; candidates: e - min < 36
//  - exact fp32 energies for candidates (block-wide dots, q row in smem)
//  - exact softmax weights over candidates (dropped terms < 2e-15 each)
//  - sparse gather out = sum w_d * kv[d,:], then per-64 softmax -> d_out
// One block (256 threads) per (b,c) row.
// ---------------------------------------------------------------------------
__global__ __launch_bounds__(256) void attn_apply_kernel(const float* __restrict__ q,
                                                         const float* __restrict__ kv,
                                                         float* __restrict__ out) {
    const int row = blockIdx.x;            // b*512 + c
    const int b   = row >> 9;
    const float* E    = g_energy + (size_t)row * CDIM;
    const float* qrow = q + (size_t)row * NDIM;
    const float* kvb  = kv + (size_t)b * CDIM * NDIM;
    float* O = out + (size_t)row * NDIM;

    __shared__ float sRed[8];
    __shared__ float sBuf[NDIM];    // q row, later reused for out row
    __shared__ float sEW[CDIM];     // exact energies, then weights
    __shared__ int   sIdx[CDIM];
    __shared__ int   sCount;

    const int t    = threadIdx.x;
    const int lane = t & 31;
    const int wp   = t >> 5;

    const float e0 = E[t];
    const float e1 = E[t + 256];

    // ---- approx min over the 512 energies ----
    float mn = fminf(e0, e1);
#pragma unroll
    for (int off = 16; off > 0; off >>= 1)
        mn = fminf(mn, __shfl_xor_sync(0xffffffffu, mn, off));
    if (lane == 0) sRed[wp] = mn;
    if (t == 0) sCount = 0;
    __syncthreads();
    mn = sRed[0];
#pragma unroll
    for (int i = 1; i < 8; i++) mn = fminf(mn, sRed[i]);

    // ---- candidate selection + stage q row in smem ----
    if (e0 - mn < 36.0f) { int k = atomicAdd(&sCount, 1); sIdx[k] = t; }
    if (e1 - mn < 36.0f) { int k = atomicAdd(&sCount, 1); sIdx[k] = t + 256; }
#pragma unroll
    for (int j = 0; j < 16; j++) sBuf[t + 256 * j] = qrow[t + 256 * j];
    __syncthreads();
    const int cnt = sCount;

    // ---- exact fp32 energies for candidates (block-wide dot per candidate) ----
    for (int i = 0; i < cnt; i++) {
        const float* kr = kvb + (size_t)sIdx[i] * NDIM;
        float sum = 0.0f;
#pragma unroll
        for (int j = 0; j < 16; j++)
            sum += sBuf[t + 256 * j] * __ldg(&kr[t + 256 * j]);
#pragma unroll
        for (int off = 16; off > 0; off >>= 1)
            sum += __shfl_xor_sync(0xffffffffu, sum, off);
        if (lane == 0) sRed[wp] = sum;
        __syncthreads();
        if (t == 0) {
            float tot = 0.0f;
#pragma unroll
            for (int w = 0; w < 8; w++) tot += sRed[w];
            sEW[i] = tot;
        }
        __syncthreads();
    }

    // ---- exact min + denominator over candidates (all threads identical) ----
    float m = 3.4e38f;
    for (int i = 0; i < cnt; i++) m = fminf(m, sEW[i]);
    float s = 0.0f;
    for (int i = 0; i < cnt; i++) s += expf(m - sEW[i]);
    const float inv = 1.0f / s;
    __syncthreads();
    for (int i = t; i < cnt; i += 256)
        sEW[i] = expf(m - sEW[i]) * inv;   // in-place weights
    __syncthreads();

    // ---- sparse gather-accumulate ----
    float acc[16];
#pragma unroll
    for (int k = 0; k < 16; k++) acc[k] = 0.0f;
    for (int i = 0; i < cnt; i++) {
        const float* kr = kvb + (size_t)sIdx[i] * NDIM;
        const float w = sEW[i];
#pragma unroll
        for (int k = 0; k < 16; k++)
            acc[k] += w * __ldg(&kr[t + 256 * k]);
    }
    __syncthreads();   // done with sBuf-as-q
#pragma unroll
    for (int k = 0; k < 16; k++) sBuf[t + 256 * k] = acc[k];
    __syncthreads();

    // ---- final softmax over each 64-wide segment; 8 warps x 8 segments ----
#pragma unroll
    for (int sgi = 0; sgi < 8; sgi++) {
        const int base = (wp * 8 + sgi) * 64;
        const float v0 = sBuf[base + lane];
        const float v1 = sBuf[base + lane + 32];
        float mx = fmaxf(v0, v1);
#pragma unroll
        for (int off = 16; off > 0; off >>= 1)
            mx = fmaxf(mx, __shfl_xor_sync(0xffffffffu, mx, off));
        const float q0 = expf(v0 - mx);
        const float q1 = expf(v1 - mx);
        float ss = q0 + q1;
#pragma unroll
        for (int off = 16; off > 0; off >>= 1)
            ss += __shfl_xor_sync(0xffffffffu, ss, off);
        const float iv = 1.0f / ss;
        O[base + lane]      = q0 * iv;
        O[base + lane + 32] = q1 * iv;
    }
}

// ---------------------------------------------------------------------------
extern "C" void kernel_launch(void* const* d_in, const int* in_sizes, int n_in,
                              void* d_out, int out_size) {
    const float* kv = (const float*)d_in[0];  // x_training
    const float* q  = (const float*)d_in[1];  // x_pre
    float* out = (float*)d_out;

    cudaFuncSetAttribute(hgemm_kernel,
                         cudaFuncAttributeMaxDynamicSharedMemorySize, HGEMM_SMEM);

    convert_kernel<<<TOT_ELEMS / 4 / 256, 256>>>((const float4*)q, (const float4*)kv);

    dim3 g1(CDIM / BN, CDIM / BM, BATCH);   // (4, 4, 16)
    hgemm_kernel<<<g1, 256, HGEMM_SMEM>>>();

    attn_apply_kernel<<<BATCH * CDIM, 256>>>(q, kv, out);
}

// round 17
// speedup vs baseline: 1.1396x; 1.0025x over previous
#include <cuda_runtime.h>
#include <cuda_fp16.h>
#include <cstdint>
#include <math.h>

#define BATCH 16
#define CDIM  512
#define HH    64
#define WW    64
#define NDIM  4096  // H*W
#define TOT_ELEMS (BATCH * CDIM * NDIM)   // 33,554,432

// Scratch (allocation-guard safe): fp16 copies of inputs + fp32 energy.
__device__ __half g_hq [TOT_ELEMS];
__device__ __half g_hkv[TOT_ELEMS];
__device__ float  g_energy[BATCH * (size_t)CDIM * CDIM];

// ---------------------------------------------------------------------------
// Convert fp32 inputs to fp16 scratch. One float4 per tensor per thread.
// (83% DRAM roofline already)
// ---------------------------------------------------------------------------
__global__ __launch_bounds__(256) void convert_kernel(const float4* __restrict__ q4,
                                                      const float4* __restrict__ kv4) {
    const int i = blockIdx.x * 256 + threadIdx.x;     // < TOT_ELEMS/4
    float4 a = q4[i];
    float4 b = kv4[i];
    __half2* hq  = (__half2*)g_hq;
    __half2* hkv = (__half2*)g_hkv;
    hq [2 * i]     = __floats2half2_rn(a.x, a.y);
    hq [2 * i + 1] = __floats2half2_rn(a.z, a.w);
    hkv[2 * i]     = __floats2half2_rn(b.x, b.y);
    hkv[2 * i + 1] = __floats2half2_rn(b.z, b.w);
}

// ---------------------------------------------------------------------------
// HGEMM: approx energy[b,c,d] = sum_n q[c,n]*kv[d,n], fp16 in, fp32 acc.
// Tile BM=128 x BN=128, BK=64 halves (128 B rows, xor-8 swizzle).
// 256 threads = 8 warps (2 m x 4 n), warp tile 64x32, mma.m16n8k16.
// cp.async double-buffered smem pipeline (64 KB dynamic).
// ---------------------------------------------------------------------------
#define BM 128
#define BN 128
#define BK 64
#define HGEMM_SMEM (2 * (BM + BN) * BK * 2)   // 65536 bytes

__device__ __forceinline__ int sw_idx(int row, int chunk) {
    return row * BK + ((chunk ^ (row & 7)) << 3);
}

__device__ __forceinline__ void ldsm4(uint32_t& r0, uint32_t& r1, uint32_t& r2,
                                      uint32_t& r3, uint32_t addr) {
    asm volatile("ldmatrix.sync.aligned.m8n8.x4.shared.b16 {%0,%1,%2,%3}, [%4];"
                 : "=r"(r0), "=r"(r1), "=r"(r2), "=r"(r3) : "r"(addr));
}

__device__ __forceinline__ void mma16816(float* c, const uint32_t* a, const uint32_t* b) {
    asm volatile("mma.sync.aligned.m16n8k16.row.col.f32.f16.f16.f32 "
                 "{%0,%1,%2,%3}, {%4,%5,%6,%7}, {%8,%9}, {%0,%1,%2,%3};"
                 : "+f"(c[0]), "+f"(c[1]), "+f"(c[2]), "+f"(c[3])
                 : "r"(a[0]), "r"(a[1]), "r"(a[2]), "r"(a[3]),
                   "r"(b[0]), "r"(b[1]));
}

__device__ __forceinline__ void cp_async16(uint32_t dst, const void* src) {
    asm volatile("cp.async.cg.shared.global [%0], [%1], 16;" :: "r"(dst), "l"(src));
}
__device__ __forceinline__ void cp_commit() {
    asm volatile("cp.async.commit_group;");
}
template<int N> __device__ __forceinline__ void cp_wait() {
    asm volatile("cp.async.wait_group %0;" :: "n"(N));
}

__global__ __launch_bounds__(256) void hgemm_kernel() {
    extern __shared__ __align__(16) __half dynsmem[];
    __half* As = dynsmem;                  // [2][BM*BK]
    __half* Bs = dynsmem + 2 * BM * BK;    // [2][BN*BK]

    const int b = blockIdx.z;
    const __half* Ab = g_hq  + (size_t)b * CDIM * NDIM + (size_t)blockIdx.y * BM * NDIM;
    const __half* Bb = g_hkv + (size_t)b * CDIM * NDIM + (size_t)blockIdx.x * BN * NDIM;

    const int t    = threadIdx.x;
    const int lane = t & 31;
    const int wid  = t >> 5;
    const int wm   = wid & 1;          // 0..1 -> m offset (64)
    const int wn   = wid >> 1;         // 0..3 -> n offset (32)
    const int mbase = wm * 64;
    const int nbase = wn * 32;

    // global-load mapping: 8 threads per 128-B row
    const int ldRow   = t >> 3;        // 0..31
    const int ldChunk = t & 7;         // 0..7

    const uint32_t asU = (uint32_t)__cvta_generic_to_shared(As);
    const uint32_t bsU = (uint32_t)__cvta_generic_to_shared(Bs);

    float acc[4][4][4];
#pragma unroll
    for (int mi = 0; mi < 4; mi++)
#pragma unroll
        for (int ni = 0; ni < 4; ni++)
#pragma unroll
            for (int k = 0; k < 4; k++) acc[mi][ni][k] = 0.0f;

    // async stage loader
    auto load_stage = [&](int stage, int kk) {
        const __half* gpa = Ab + kk * BK + ldChunk * 8;
        const __half* gpb = Bb + kk * BK + ldChunk * 8;
        const uint32_t aS = asU + (uint32_t)(stage * BM * BK * 2);
        const uint32_t bS = bsU + (uint32_t)(stage * BN * BK * 2);
#pragma unroll
        for (int i = 0; i < 4; i++) {
            int r = ldRow + i * 32;
            cp_async16(aS + (uint32_t)(sw_idx(r, ldChunk) * 2), gpa + (size_t)r * NDIM);
        }
#pragma unroll
        for (int i = 0; i < 4; i++) {
            int r = ldRow + i * 32;
            cp_async16(bS + (uint32_t)(sw_idx(r, ldChunk) * 2), gpb + (size_t)r * NDIM);
        }
        cp_commit();
    };

    const int NCHUNK = NDIM / BK;   // 64
    load_stage(0, 0);

    for (int kk = 0; kk < NCHUNK; kk++) {
        if (kk + 1 < NCHUNK) {
            load_stage((kk + 1) & 1, kk + 1);
            cp_wait<1>();
        } else {
            cp_wait<0>();
        }
        __syncthreads();

        const uint32_t aS = asU + (uint32_t)((kk & 1) * BM * BK * 2);
        const uint32_t bS = bsU + (uint32_t)((kk & 1) * BN * BK * 2);

#pragma unroll
        for (int s = 0; s < 4; s++) {
            uint32_t afr[4][4];
            uint32_t bfr[4][2];
#pragma unroll
            for (int mi = 0; mi < 4; mi++) {
                int row   = mbase + mi * 16 + (lane & 15);
                int chunk = 2 * s + (lane >> 4);
                ldsm4(afr[mi][0], afr[mi][1], afr[mi][2], afr[mi][3],
                      aS + (uint32_t)(sw_idx(row, chunk) * 2));
            }
#pragma unroll
            for (int p = 0; p < 2; p++) {
                int row   = nbase + p * 16 + (lane & 7) + ((lane >> 4) << 3);
                int chunk = 2 * s + ((lane >> 3) & 1);
                ldsm4(bfr[2 * p][0], bfr[2 * p][1], bfr[2 * p + 1][0], bfr[2 * p + 1][1],
                      bS + (uint32_t)(sw_idx(row, chunk) * 2));
            }
#pragma unroll
            for (int mi = 0; mi < 4; mi++)
#pragma unroll
                for (int ni = 0; ni < 4; ni++)
                    mma16816(acc[mi][ni], afr[mi], bfr[ni]);
        }
        __syncthreads();
    }

    // ---- epilogue: write fp32 energies ----
    float* Eb = g_energy + (size_t)b * CDIM * CDIM;
    const int c0 = blockIdx.y * BM + mbase;
    const int d0 = blockIdx.x * BN + nbase;
#pragma unroll
    for (int mi = 0; mi < 4; mi++) {
#pragma unroll
        for (int ni = 0; ni < 4; ni++) {
            int r = c0 + mi * 16 + (lane >> 2);
            int c = d0 + ni * 8 + ((lane & 3) << 1);
            Eb[(size_t)r * CDIM + c]           = acc[mi][ni][0];
            Eb[(size_t)r * CDIM + c + 1]       = acc[mi][ni][1];
            Eb[(size_t)(r + 8) * CDIM + c]     = acc[mi][ni][2];
            Eb[(size_t)(r + 8) * CDIM + c + 1] = acc[mi][ni][3];
        }
    }
}

// ---------------------------------------------------------------------------
// Fused attention-apply:
//  - approx min over row energies; candidates: e - min < 36
//  - exact fp32 energies for candidates (block-wide dots, q row in smem)
//  - exact softmax weights over candidates (dropped terms < 2e-15 each)
//  - sparse gather out = sum w_d * kv[d,:], then per-64 softmax -> d_out
// One block (256 threads) per (b,c) row.
// ---------------------------------------------------------------------------
__global__ __launch_bounds__(256) void attn_apply_kernel(const float* __restrict__ q,
                                                         const float* __restrict__ kv,
                                                         float* __restrict__ out) {
    const int row = blockIdx.x;            // b*512 + c
    const int b   = row >> 9;
    const float* E    = g_energy + (size_t)row * CDIM;
    const float* qrow = q + (size_t)row * NDIM;
    const float* kvb  = kv + (size_t)b * CDIM * NDIM;
    float* O = out + (size_t)row * NDIM;

    __shared__ float sRed[8];
    __shared__ float sBuf[NDIM];    // q row, later reused for out row
    __shared__ float sEW[CDIM];     // exact energies, then weights
    __shared__ int   sIdx[CDIM];
    __shared__ int   sCount;

    const int t    = threadIdx.x;
    const int lane = t & 31;
    const int wp   = t >> 5;

    const float e0 = E[t];
    const float e1 = E[t + 256];

    // ---- approx min over the 512 energies ----
    float mn = fminf(e0, e1);
#pragma unroll
    for (int off = 16; off > 0; off >>= 1)
        mn = fminf(mn, __shfl_xor_sync(0xffffffffu, mn, off));
    if (lane == 0) sRed[wp] = mn;
    if (t == 0) sCount = 0;
    __syncthreads();
    mn = sRed[0];
#pragma unroll
    for (int i = 1; i < 8; i++) mn = fminf(mn, sRed[i]);

    // ---- candidate selection + stage q row in smem ----
    if (e0 - mn < 36.0f) { int k = atomicAdd(&sCount, 1); sIdx[k] = t; }
    if (e1 - mn < 36.0f) { int k = atomicAdd(&sCount, 1); sIdx[k] = t + 256; }
#pragma unroll
    for (int j = 0; j < 16; j++) sBuf[t + 256 * j] = qrow[t + 256 * j];
    __syncthreads();
    const int cnt = sCount;

    // ---- exact fp32 energies for candidates (block-wide dot per candidate) ----
    for (int i = 0; i < cnt; i++) {
        const float* kr = kvb + (size_t)sIdx[i] * NDIM;
        float sum = 0.0f;
#pragma unroll
        for (int j = 0; j < 16; j++)
            sum += sBuf[t + 256 * j] * __ldg(&kr[t + 256 * j]);
#pragma unroll
        for (int off = 16; off > 0; off >>= 1)
            sum += __shfl_xor_sync(0xffffffffu, sum, off);
        if (lane == 0) sRed[wp] = sum;
        __syncthreads();
        if (t == 0) {
            float tot = 0.0f;
#pragma unroll
            for (int w = 0; w < 8; w++) tot += sRed[w];
            sEW[i] = tot;
        }
        __syncthreads();
    }

    // ---- exact min + denominator over candidates (all threads identical) ----
    float m = 3.4e38f;
    for (int i = 0; i < cnt; i++) m = fminf(m, sEW[i]);
    float s = 0.0f;
    for (int i = 0; i < cnt; i++) s += expf(m - sEW[i]);
    const float inv = 1.0f / s;
    __syncthreads();
    for (int i = t; i < cnt; i += 256)
        sEW[i] = expf(m - sEW[i]) * inv;   // in-place weights
    __syncthreads();

    // ---- sparse gather-accumulate ----
    float acc[16];
#pragma unroll
    for (int k = 0; k < 16; k++) acc[k] = 0.0f;
    for (int i = 0; i < cnt; i++) {
        const float* kr = kvb + (size_t)sIdx[i] * NDIM;
        const float w = sEW[i];
#pragma unroll
        for (int k = 0; k < 16; k++)
            acc[k] += w * __ldg(&kr[t + 256 * k]);
    }
    __syncthreads();   // done with sBuf-as-q
#pragma unroll
    for (int k = 0; k < 16; k++) sBuf[t + 256 * k] = acc[k];
    __syncthreads();

    // ---- final softmax over each 64-wide segment; 8 warps x 8 segments ----
#pragma unroll
    for (int sgi = 0; sgi < 8; sgi++) {
        const int base = (wp * 8 + sgi) * 64;
        const float v0 = sBuf[base + lane];
        const float v1 = sBuf[base + lane + 32];
        float mx = fmaxf(v0, v1);
#pragma unroll
        for (int off = 16; off > 0; off >>= 1)
            mx = fmaxf(mx, __shfl_xor_sync(0xffffffffu, mx, off));
        const float q0 = expf(v0 - mx);
        const float q1 = expf(v1 - mx);
        float ss = q0 + q1;
#pragma unroll
        for (int off = 16; off > 0; off >>= 1)
            ss += __shfl_xor_sync(0xffffffffu, ss, off);
        const float iv = 1.0f / ss;
        O[base + lane]      = q0 * iv;
        O[base + lane + 32] = q1 * iv;
    }
}

// ---------------------------------------------------------------------------
extern "C" void kernel_launch(void* const* d_in, const int* in_sizes, int n_in,
                              void* d_out, int out_size) {
    const float* kv = (const float*)d_in[0];  // x_training
    const float* q  = (const float*)d_in[1];  // x_pre
    float* out = (float*)d_out;

    cudaFuncSetAttribute(hgemm_kernel,
                         cudaFuncAttributeMaxDynamicSharedMemorySize, HGEMM_SMEM);

    convert_kernel<<<TOT_ELEMS / 4 / 256, 256>>>((const float4*)q, (const float4*)kv);

    dim3 g1(CDIM / BN, CDIM / BM, BATCH);   // (4, 4, 16)
    hgemm_kernel<<<g1, 256, HGEMM_SMEM>>>();

    attn_apply_kernel<<<BATCH * CDIM, 256>>>(q, kv, out);
}